// round 8
// baseline (speedup 1.0000x reference)
#include <cuda_runtime.h>
#include <cstdint>

// SimpleSparseConvNet: rulebook sparse conv, Cin=1, Cout=16.
// Degree-aware quad-lane scatter (4 pairs/thread, branch-free loads).
// k_count builds the deg>=2 worklist inline (old==1 appender), so zeroing
// touches only multi-degree rows. No output memset; deg==1 rows STG.128 once.

#define MAX_NOUT (4 * 1024 * 1024)

__device__ __align__(16) unsigned int g_counts[MAX_NOUT];
__device__ __align__(16) unsigned int g_multi[MAX_NOUT];
__device__ unsigned int g_nmulti;

__device__ __forceinline__ void red_add_v4(float* addr, float a, float b, float c, float d) {
    asm volatile("red.global.add.v4.f32 [%0], {%1, %2, %3, %4};"
                 :: "l"(addr), "f"(a), "f"(b), "f"(c), "f"(d)
                 : "memory");
}

// ---- K1: histogram of out_idx, 4 streams/thread + deg>=2 worklist build ----
__global__ void __launch_bounds__(256)
k_count(const int* __restrict__ out_idx, int M, int Q) {
    int q = blockIdx.x * blockDim.x + threadIdx.x;
    if (q >= Q) return;

    const int m3 = q + 3 * Q;
    const bool v3 = (m3 < M);
    int m[4] = { q, q + Q, q + 2 * Q, v3 ? m3 : (M - 1) };

    int o[4];
#pragma unroll
    for (int r = 0; r < 4; r++) o[r] = __ldg(&out_idx[m[r]]);   // batched loads

#pragma unroll
    for (int r = 0; r < 4; r++) {
        if (r == 3 && !v3) break;                // only the atomic is guarded
        unsigned int old = atomicAdd(&g_counts[o[r]], 1u);
        if (old == 1u) {                         // exactly one appender per deg>=2 row
            unsigned int pos = atomicAdd(&g_nmulti, 1u);
            g_multi[pos] = (unsigned int)o[r];
        }
    }
}

// ---- K2: zero only deg>=2 rows, via worklist (grid-stride) -------------------
__global__ void __launch_bounds__(256)
k_zero_multi(float* __restrict__ out) {
    const unsigned int total = g_nmulti * 4u;    // 4 float4 quads per row
    const unsigned int stride = gridDim.x * blockDim.x;
    for (unsigned int idx = blockIdx.x * blockDim.x + threadIdx.x;
         idx < total; idx += stride) {
        unsigned int o = __ldg(&g_multi[idx >> 2]);   // quad-broadcast
        reinterpret_cast<float4*>(out)[(size_t)o * 4 + (idx & 3)] =
            make_float4(0.f, 0.f, 0.f, 0.f);
    }
}

// ---- K3: scatter, 4 lanes per pair, 4 pairs per quad, branch-free loads ------
__global__ void __launch_bounds__(256)
k_scatter(const float* __restrict__ feats,
          const float* __restrict__ weight,
          const int* __restrict__ in_idx,
          const int* __restrict__ out_idx,
          const int* __restrict__ k_idx,
          float* __restrict__ out,
          int M, int Q) {
    int tid = blockIdx.x * blockDim.x + threadIdx.x;
    int q = tid >> 2;
    int j = tid & 3;
    if (q >= Q) return;

    const int m3 = q + 3 * Q;
    const bool v3 = (m3 < M);
    int m[4] = { q, q + Q, q + 2 * Q, v3 ? m3 : (M - 1) };

    int o[4], k[4], ii[4];
#pragma unroll
    for (int r = 0; r < 4; r++) {
        o[r]  = __ldg(&out_idx[m[r]]);
        k[r]  = __ldg(&k_idx[m[r]]);
        ii[r] = __ldg(&in_idx[m[r]]);
    }
    float f[4];
    unsigned int d[4];
    float4 w[4];
#pragma unroll
    for (int r = 0; r < 4; r++) {
        f[r] = __ldg(&feats[ii[r]]);
        d[r] = __ldg(&g_counts[o[r]]);
        w[r] = __ldg(reinterpret_cast<const float4*>(weight) + (size_t)k[r] * 4 + j);
    }
#pragma unroll
    for (int r = 0; r < 4; r++) {
        if (r == 3 && !v3) break;
        float4 v = make_float4(f[r] * w[r].x, f[r] * w[r].y,
                               f[r] * w[r].z, f[r] * w[r].w);
        float* op = out + (size_t)o[r] * 16 + j * 4;
        if (d[r] == 1u) *reinterpret_cast<float4*>(op) = v;
        else            red_add_v4(op, v.x, v.y, v.z, v.w);
    }
}

extern "C" void kernel_launch(void* const* d_in, const int* in_sizes, int n_in,
                              void* d_out, int out_size) {
    const float* feats  = (const float*)d_in[0];
    const float* weight = (const float*)d_in[1];
    const int* in_idx   = (const int*)d_in[2];
    const int* out_idx  = (const int*)d_in[3];
    const int* k_idx    = (const int*)d_in[4];
    float* out = (float*)d_out;

    const int M = in_sizes[2];
    const int n_out = out_size / 16;
    const int Q = (M + 3) / 4;

    void* counts_ptr = nullptr;
    void* nmulti_ptr = nullptr;
    cudaGetSymbolAddress(&counts_ptr, g_counts);
    cudaGetSymbolAddress(&nmulti_ptr, g_nmulti);

    const int T = 256;
    cudaMemsetAsync(counts_ptr, 0, (size_t)n_out * sizeof(unsigned int), 0);
    cudaMemsetAsync(nmulti_ptr, 0, sizeof(unsigned int), 0);
    k_count<<<(Q + T - 1) / T, T>>>(out_idx, M, Q);
    k_zero_multi<<<148 * 8, T>>>(out);
    k_scatter<<<((size_t)Q * 4 + T - 1) / T, T>>>(feats, weight, in_idx, out_idx,
                                                  k_idx, out, M, Q);
}

// round 9
// speedup vs baseline: 1.0003x; 1.0003x over previous
#include <cuda_runtime.h>
#include <cstdint>

// SimpleSparseConvNet: rulebook sparse conv, Cin=1, Cout=16.
// Degree-aware quad-lane scatter (4 pairs/thread, branch-free loads).
// k_count builds the deg>=2 worklist with WARP-AGGREGATED appends (one
// counter atomic per warp, not per element). zero_multi walks the worklist.
// No output memset; deg==1 rows written once with STG.128.

#define MAX_NOUT (4 * 1024 * 1024)

__device__ __align__(16) unsigned int g_counts[MAX_NOUT];
__device__ __align__(16) unsigned int g_multi[MAX_NOUT];
__device__ unsigned int g_nmulti;

__device__ __forceinline__ void red_add_v4(float* addr, float a, float b, float c, float d) {
    asm volatile("red.global.add.v4.f32 [%0], {%1, %2, %3, %4};"
                 :: "l"(addr), "f"(a), "f"(b), "f"(c), "f"(d)
                 : "memory");
}

// Warp-aggregated append of `val` when `want` is true.
__device__ __forceinline__ void warp_append(bool want, unsigned int val) {
    unsigned int amask = __activemask();
    unsigned int ballot = __ballot_sync(amask, want);
    if (ballot == 0u) return;
    int leader = __ffs(ballot) - 1;
    unsigned int lane = threadIdx.x & 31u;
    unsigned int base = 0;
    if ((int)lane == leader) base = atomicAdd(&g_nmulti, (unsigned int)__popc(ballot));
    base = __shfl_sync(amask, base, leader);
    if (want) g_multi[base + __popc(ballot & ((1u << lane) - 1u))] = val;
}

// ---- K1: histogram (4 streams/thread) + aggregated deg>=2 worklist ---------
__global__ void __launch_bounds__(256)
k_count(const int* __restrict__ out_idx, int M, int Q) {
    int q = blockIdx.x * blockDim.x + threadIdx.x;
    if (q >= Q) return;

    const int m3 = q + 3 * Q;
    const bool v3 = (m3 < M);
    int m[4] = { q, q + Q, q + 2 * Q, v3 ? m3 : (M - 1) };

    int o[4];
#pragma unroll
    for (int r = 0; r < 4; r++) o[r] = __ldg(&out_idx[m[r]]);   // batched loads

#pragma unroll
    for (int r = 0; r < 4; r++) {
        bool active = (r < 3) || v3;
        unsigned int old = 0xFFFFFFFFu;
        if (active) old = atomicAdd(&g_counts[o[r]], 1u);
        warp_append(active && (old == 1u), (unsigned int)o[r]);
    }
}

// ---- K2: zero only deg>=2 rows via worklist (grid-stride) --------------------
__global__ void __launch_bounds__(256)
k_zero_multi(float* __restrict__ out) {
    const unsigned int total = g_nmulti * 4u;    // 4 float4 quads per row
    const unsigned int stride = gridDim.x * blockDim.x;
    for (unsigned int idx = blockIdx.x * blockDim.x + threadIdx.x;
         idx < total; idx += stride) {
        unsigned int o = __ldg(&g_multi[idx >> 2]);   // quad-broadcast
        reinterpret_cast<float4*>(out)[(size_t)o * 4 + (idx & 3)] =
            make_float4(0.f, 0.f, 0.f, 0.f);
    }
}

// ---- K3: scatter, 4 lanes per pair, 4 pairs per quad, branch-free loads ------
__global__ void __launch_bounds__(256)
k_scatter(const float* __restrict__ feats,
          const float* __restrict__ weight,
          const int* __restrict__ in_idx,
          const int* __restrict__ out_idx,
          const int* __restrict__ k_idx,
          float* __restrict__ out,
          int M, int Q) {
    int tid = blockIdx.x * blockDim.x + threadIdx.x;
    int q = tid >> 2;
    int j = tid & 3;
    if (q >= Q) return;

    const int m3 = q + 3 * Q;
    const bool v3 = (m3 < M);
    int m[4] = { q, q + Q, q + 2 * Q, v3 ? m3 : (M - 1) };

    int o[4], k[4], ii[4];
#pragma unroll
    for (int r = 0; r < 4; r++) {
        o[r]  = __ldg(&out_idx[m[r]]);
        k[r]  = __ldg(&k_idx[m[r]]);
        ii[r] = __ldg(&in_idx[m[r]]);
    }
    float f[4];
    unsigned int d[4];
    float4 w[4];
#pragma unroll
    for (int r = 0; r < 4; r++) {
        f[r] = __ldg(&feats[ii[r]]);
        d[r] = __ldg(&g_counts[o[r]]);
        w[r] = __ldg(reinterpret_cast<const float4*>(weight) + (size_t)k[r] * 4 + j);
    }
#pragma unroll
    for (int r = 0; r < 4; r++) {
        if (r == 3 && !v3) break;
        float4 v = make_float4(f[r] * w[r].x, f[r] * w[r].y,
                               f[r] * w[r].z, f[r] * w[r].w);
        float* op = out + (size_t)o[r] * 16 + j * 4;
        if (d[r] == 1u) *reinterpret_cast<float4*>(op) = v;
        else            red_add_v4(op, v.x, v.y, v.z, v.w);
    }
}

extern "C" void kernel_launch(void* const* d_in, const int* in_sizes, int n_in,
                              void* d_out, int out_size) {
    const float* feats  = (const float*)d_in[0];
    const float* weight = (const float*)d_in[1];
    const int* in_idx   = (const int*)d_in[2];
    const int* out_idx  = (const int*)d_in[3];
    const int* k_idx    = (const int*)d_in[4];
    float* out = (float*)d_out;

    const int M = in_sizes[2];
    const int n_out = out_size / 16;
    const int Q = (M + 3) / 4;

    void* counts_ptr = nullptr;
    void* nmulti_ptr = nullptr;
    cudaGetSymbolAddress(&counts_ptr, g_counts);
    cudaGetSymbolAddress(&nmulti_ptr, g_nmulti);

    const int T = 256;
    cudaMemsetAsync(counts_ptr, 0, (size_t)n_out * sizeof(unsigned int), 0);
    cudaMemsetAsync(nmulti_ptr, 0, sizeof(unsigned int), 0);
    k_count<<<(Q + T - 1) / T, T>>>(out_idx, M, Q);
    k_zero_multi<<<148 * 8, T>>>(out);
    k_scatter<<<((size_t)Q * 4 + T - 1) / T, T>>>(feats, weight, in_idx, out_idx,
                                                  k_idx, out, M, Q);
}

// round 10
// speedup vs baseline: 1.4990x; 1.4986x over previous
#include <cuda_runtime.h>
#include <cstdint>

// SimpleSparseConvNet: rulebook sparse conv, Cin=1, Cout=16.
// R7 skeleton: word counts via fire-and-forget RED histogram, scan-based
// zeroing of deg>=2 rows, degree-aware quad-lane scatter.
// R10: 4-stream ILP in k_count (plain RED), 8-stream ILP in k_scatter.

#define MAX_NOUT (4 * 1024 * 1024)

__device__ __align__(16) unsigned int g_counts[MAX_NOUT];

__device__ __forceinline__ void red_add_v4(float* addr, float a, float b, float c, float d) {
    asm volatile("red.global.add.v4.f32 [%0], {%1, %2, %3, %4};"
                 :: "l"(addr), "f"(a), "f"(b), "f"(c), "f"(d)
                 : "memory");
}

// ---- K1: histogram of out_idx, 4 streams/thread, RED only -------------------
__global__ void __launch_bounds__(256)
k_count(const int* __restrict__ out_idx, int M, int Q) {
    int q = blockIdx.x * blockDim.x + threadIdx.x;
    if (q >= Q) return;

    const int m3 = q + 3 * Q;
    const bool v3 = (m3 < M);
    int m[4] = { q, q + Q, q + 2 * Q, v3 ? m3 : (M - 1) };

    int o[4];
#pragma unroll
    for (int r = 0; r < 4; r++) o[r] = __ldg(&out_idx[m[r]]);   // batched loads

    atomicAdd(&g_counts[o[0]], 1u);      // RED (result unused)
    atomicAdd(&g_counts[o[1]], 1u);
    atomicAdd(&g_counts[o[2]], 1u);
    if (v3) atomicAdd(&g_counts[o[3]], 1u);
}

// ---- K2: zero output rows with deg >= 2 (thread per float4, coalesced) ------
__global__ void __launch_bounds__(256)
k_zero_multi(float* __restrict__ out, int n_out) {
    int tid = blockIdx.x * blockDim.x + threadIdx.x;
    int o = tid >> 2;
    if (o >= n_out) return;
    if (__ldg(&g_counts[o]) >= 2u) {
        reinterpret_cast<float4*>(out)[tid] = make_float4(0.f, 0.f, 0.f, 0.f);
    }
}

// ---- K3: scatter, 4 lanes per pair, 8 pairs per quad, branch-free loads ------
#define NS 8
__global__ void __launch_bounds__(256)
k_scatter(const float* __restrict__ feats,
          const float* __restrict__ weight,
          const int* __restrict__ in_idx,
          const int* __restrict__ out_idx,
          const int* __restrict__ k_idx,
          float* __restrict__ out,
          int M, int Q) {
    int tid = blockIdx.x * blockDim.x + threadIdx.x;
    int q = tid >> 2;
    int j = tid & 3;
    if (q >= Q) return;

    // Streams 0..NS-2 always valid for q < Q (M >= (NS-1)Q - ...); last clamped.
    const int mLast = q + (NS - 1) * Q;
    const bool vLast = (mLast < M);
    int m[NS];
#pragma unroll
    for (int r = 0; r < NS - 1; r++) m[r] = q + r * Q;
    m[NS - 1] = vLast ? mLast : (M - 1);

    int o[NS], k[NS], ii[NS];
#pragma unroll
    for (int r = 0; r < NS; r++) {
        o[r]  = __ldg(&out_idx[m[r]]);
        k[r]  = __ldg(&k_idx[m[r]]);
        ii[r] = __ldg(&in_idx[m[r]]);
    }
    float f[NS];
    unsigned int d[NS];
    float4 w[NS];
#pragma unroll
    for (int r = 0; r < NS; r++) {
        f[r] = __ldg(&feats[ii[r]]);
        d[r] = __ldg(&g_counts[o[r]]);
        w[r] = __ldg(reinterpret_cast<const float4*>(weight) + (size_t)k[r] * 4 + j);
    }
#pragma unroll
    for (int r = 0; r < NS; r++) {
        if (r == NS - 1 && !vLast) break;
        float4 v = make_float4(f[r] * w[r].x, f[r] * w[r].y,
                               f[r] * w[r].z, f[r] * w[r].w);
        float* op = out + (size_t)o[r] * 16 + j * 4;
        if (d[r] == 1u) *reinterpret_cast<float4*>(op) = v;
        else            red_add_v4(op, v.x, v.y, v.z, v.w);
    }
}

extern "C" void kernel_launch(void* const* d_in, const int* in_sizes, int n_in,
                              void* d_out, int out_size) {
    const float* feats  = (const float*)d_in[0];
    const float* weight = (const float*)d_in[1];
    const int* in_idx   = (const int*)d_in[2];
    const int* out_idx  = (const int*)d_in[3];
    const int* k_idx    = (const int*)d_in[4];
    float* out = (float*)d_out;

    const int M = in_sizes[2];
    const int n_out = out_size / 16;
    const int Qc = (M + 3) / 4;          // count streams
    const int Qs = (M + NS - 1) / NS;    // scatter streams

    void* counts_ptr = nullptr;
    cudaGetSymbolAddress(&counts_ptr, g_counts);

    const int T = 256;
    cudaMemsetAsync(counts_ptr, 0, (size_t)n_out * sizeof(unsigned int), 0);
    k_count<<<(Qc + T - 1) / T, T>>>(out_idx, M, Qc);
    k_zero_multi<<<((size_t)n_out * 4 + T - 1) / T, T>>>(out, n_out);
    k_scatter<<<((size_t)Qs * 4 + T - 1) / T, T>>>(feats, weight, in_idx, out_idx,
                                                   k_idx, out, M, Qs);
}

// round 11
// speedup vs baseline: 1.7814x; 1.1884x over previous
#include <cuda_runtime.h>
#include <cstdint>

// SimpleSparseConvNet: rulebook sparse conv, Cin=1, Cout=16.
// Segment-aligned degree-aware scatter:
//  - k_count: byte histogram of out_idx (RED, no return) + segment-boundary
//    extraction from k_idx (rulebook is sorted by k, then o).
//  - k_zero_multi: zero only deg>=2 rows.
//  - k_scatter: grid (27, Y); blockIdx.x = segment, so all 27 segments are
//    processed at the same fractional position concurrently -> contributions
//    to the same output row land close in time (L2-resident RMW). k is
//    uniform per block: weight hoisted, no k_idx reads.

#define MAX_NOUT (4 * 1024 * 1024)
#define NS 4
#define CH (64 * NS)          // entries per block-chunk

__device__ __align__(16) unsigned char g_counts[MAX_NOUT];
__device__ unsigned int g_segstart[32];

__device__ __forceinline__ void red_add_v4(float* addr, float a, float b, float c, float d) {
    asm volatile("red.global.add.v4.f32 [%0], {%1, %2, %3, %4};"
                 :: "l"(addr), "f"(a), "f"(b), "f"(c), "f"(d)
                 : "memory");
}

// ---- K1: byte histogram (4 strided streams) + segment boundaries -----------
__global__ void __launch_bounds__(256)
k_count(const int* __restrict__ out_idx, const int* __restrict__ k_idx,
        int M, int Q) {
    int q = blockIdx.x * blockDim.x + threadIdx.x;
    if (q >= Q) return;

    const int m3 = q + 3 * Q;
    const bool v3 = (m3 < M);
    int m[4] = { q, q + Q, q + 2 * Q, v3 ? m3 : (M - 1) };

    int o[4], kk[4], kp[4];
#pragma unroll
    for (int r = 0; r < 4; r++) {
        o[r]  = __ldg(&out_idx[m[r]]);
        kk[r] = __ldg(&k_idx[m[r]]);
        kp[r] = (m[r] > 0) ? __ldg(&k_idx[m[r] - 1]) : -1;
    }
#pragma unroll
    for (int r = 0; r < 4; r++) {
        if (r < 3 || v3)
            atomicAdd(reinterpret_cast<unsigned int*>(g_counts) + (o[r] >> 2),
                      1u << ((o[r] & 3) * 8));
        // boundary writes: idempotent plain stores (safe on clamped duplicate)
        if (kp[r] < kk[r]) {
            for (int t = kp[r] + 1; t <= kk[r]; t++)
                g_segstart[t] = (unsigned int)m[r];
        }
        if (m[r] == M - 1) {
            for (int t = kk[r] + 1; t <= 27; t++)
                g_segstart[t] = (unsigned int)M;
        }
    }
}

// ---- K2: zero output rows with deg >= 2 (thread per float4, coalesced) ------
__global__ void __launch_bounds__(256)
k_zero_multi(float* __restrict__ out, int n_out) {
    int tid = blockIdx.x * blockDim.x + threadIdx.x;
    int o = tid >> 2;
    if (o >= n_out) return;
    if (__ldg(&g_counts[o]) >= 2)
        reinterpret_cast<float4*>(out)[tid] = make_float4(0.f, 0.f, 0.f, 0.f);
}

// ---- K3: segment-aligned scatter --------------------------------------------
__global__ void __launch_bounds__(256)
k_scatter(const float* __restrict__ feats,
          const float* __restrict__ weight,
          const int* __restrict__ in_idx,
          const int* __restrict__ out_idx,
          float* __restrict__ out) {
    const int s = blockIdx.x;                 // segment 0..26
    const unsigned int S = g_segstart[s];
    const unsigned int E = g_segstart[s + 1];

    const int tid = threadIdx.x;
    const int qq = tid >> 2;                  // quad id 0..63
    const int j = tid & 3;                    // float4 quad of the row

    // weight uniform per (segment, j): one load per thread for whole block
    const float4 wj = __ldg(reinterpret_cast<const float4*>(weight) + s * 4 + j);

    for (unsigned int base = S + blockIdx.y * CH; base < E;
         base += gridDim.y * CH) {
        unsigned int m[NS];
        bool vl[NS];
#pragma unroll
        for (int r = 0; r < NS; r++) {
            unsigned int mm = base + r * 64 + qq;
            vl[r] = (mm < E);
            m[r] = vl[r] ? mm : (E - 1);
        }
        int o[NS], ii[NS];
#pragma unroll
        for (int r = 0; r < NS; r++) {
            o[r]  = __ldg(&out_idx[m[r]]);
            ii[r] = __ldg(&in_idx[m[r]]);
        }
        float f[NS];
        unsigned char d[NS];
#pragma unroll
        for (int r = 0; r < NS; r++) {
            f[r] = __ldg(&feats[ii[r]]);
            d[r] = __ldg(&g_counts[o[r]]);
        }
#pragma unroll
        for (int r = 0; r < NS; r++) {
            if (vl[r]) {
                float4 v = make_float4(f[r] * wj.x, f[r] * wj.y,
                                       f[r] * wj.z, f[r] * wj.w);
                float* op = out + (size_t)o[r] * 16 + j * 4;
                if (d[r] == 1) *reinterpret_cast<float4*>(op) = v;
                else           red_add_v4(op, v.x, v.y, v.z, v.w);
            }
        }
    }
}

extern "C" void kernel_launch(void* const* d_in, const int* in_sizes, int n_in,
                              void* d_out, int out_size) {
    const float* feats  = (const float*)d_in[0];
    const float* weight = (const float*)d_in[1];
    const int* in_idx   = (const int*)d_in[2];
    const int* out_idx  = (const int*)d_in[3];
    const int* k_idx    = (const int*)d_in[4];
    float* out = (float*)d_out;

    const int M = in_sizes[2];
    const int n_out = out_size / 16;
    const int Qc = (M + 3) / 4;

    void* counts_ptr = nullptr;
    cudaGetSymbolAddress(&counts_ptr, g_counts);

    const int T = 256;
    cudaMemsetAsync(counts_ptr, 0, (size_t)((n_out + 3) & ~3), 0);
    k_count<<<(Qc + T - 1) / T, T>>>(out_idx, k_idx, M, Qc);
    k_zero_multi<<<((size_t)n_out * 4 + T - 1) / T, T>>>(out, n_out);

    dim3 grid(27, 512);   // x = segment (fastest-varying -> lockstep fractions)
    k_scatter<<<grid, T>>>(feats, weight, in_idx, out_idx, out);
}